// round 2
// baseline (speedup 1.0000x reference)
#include <cuda_runtime.h>

typedef unsigned long long u64;

#define N_AGENTS 4096
#define TOPK 12
#define SEL 16
#define EPSC 1e-4f
#define WPB 8
#define BUFD 6

__device__ float g_W2t[64 * 128];   // [i][o]
__device__ float g_W3t[128 * 64];   // [i][o]
__device__ int   g_idx[N_AGENTS * TOPK];
__device__ float g_dn [N_AGENTS * TOPK];

static __device__ __forceinline__ u64 umin64(u64 a, u64 b) { return a < b ? a : b; }
static __device__ __forceinline__ u64 pack2(float w) {
    u64 r; asm("mov.b64 %0, {%1, %1};" : "=l"(r) : "f"(w)); return r;
}
static __device__ __forceinline__ void ffma2(u64 &d, u64 a, u64 b) {
    asm("fma.rn.f32x2 %0, %1, %2, %0;" : "+l"(d) : "l"(a), "l"(b));
}
static __device__ __forceinline__ float2 unpack2(u64 v) {
    return make_float2(__uint_as_float((unsigned)v), __uint_as_float((unsigned)(v >> 32)));
}

// ============================ weight transpose ============================
__global__ void transpose_kernel(const float* __restrict__ W2, const float* __restrict__ W3) {
    int t = blockIdx.x * blockDim.x + threadIdx.x;
    if (t < 128 * 64) {
        int o2 = t / 64, i2 = t % 64;      // W2: [128][64]
        g_W2t[i2 * 128 + o2] = W2[t];
        int o3 = t / 128, i3 = t % 128;    // W3: [64][128]
        g_W3t[i3 * 64 + o3] = W3[t];
    }
}

// ============================ exact top-k ============================
static __device__ __forceinline__ void warp_merge(
    u64 &topent, u64 &thrkey, int &bcnt, u64 (*buf)[32], int lane)
{
    u64 v[BUFD];
#pragma unroll
    for (int s = 0; s < BUFD; s++) v[s] = (s < bcnt) ? buf[s][lane] : ~0ULL;
    u64 oldtop = topent;
    u64 newtop = ~0ULL;
#pragma unroll 1
    for (int r = 0; r < SEL; r++) {
        u64 lm = oldtop;
#pragma unroll
        for (int s = 0; s < BUFD; s++) lm = umin64(lm, v[s]);
#pragma unroll
        for (int o = 16; o > 0; o >>= 1)
            lm = umin64(lm, __shfl_xor_sync(0xffffffffu, lm, o));
        if (oldtop == lm) oldtop = ~0ULL;
#pragma unroll
        for (int s = 0; s < BUFD; s++) if (v[s] == lm) v[s] = ~0ULL;
        if (lane == r) newtop = lm;
        thrkey = lm;
    }
    topent = newtop;
    bcnt = 0;
}

__global__ __launch_bounds__(256) void topk_kernel(const float4* __restrict__ states)
{
    __shared__ float2 sxy[N_AGENTS];
    __shared__ u64 sbuf[WPB][BUFD][32];

    for (int j = threadIdx.x; j < N_AGENTS; j += 256) {
        float4 s = states[j];
        sxy[j] = make_float2(s.x, s.y);
    }
    __syncthreads();

    const int warp = threadIdx.x >> 5;
    const int lane = threadIdx.x & 31;
    const int row  = blockIdx.x * WPB + warp;
    const float xi = sxy[row].x, yi = sxy[row].y;

    u64 topent = ~0ULL, thrkey = ~0ULL;
    int bcnt = 0;

#pragma unroll 1
    for (int m = 0; m < N_AGENTS / 32; m++) {
        int j = m * 32 + lane;
        float2 sj = sxy[j];
        float dx = __fsub_rn(xi, sj.x);
        float dy = __fsub_rn(yi, sj.y);
        float pa = __fadd_rn(__fmul_rn(dx, dx), EPSC);
        float pb = __fadd_rn(__fmul_rn(dy, dy), EPSC);
        float d2 = __fadd_rn(pa, pb);
        u64 key = ((u64)__float_as_uint(d2) << 32) | (unsigned)j;
        if (key < thrkey) { sbuf[warp][bcnt][lane] = key; bcnt++; }
        if (__ballot_sync(0xffffffffu, bcnt == BUFD))
            warp_merge(topent, thrkey, bcnt, sbuf[warp], lane);
    }
    if (__ballot_sync(0xffffffffu, bcnt > 0))
        warp_merge(topent, thrkey, bcnt, sbuf[warp], lane);

    // re-rank survivors by (dn, idx) — JAX top_k tie semantics
    float d2v = __uint_as_float((unsigned)(topent >> 32));
    int   jv  = (int)(unsigned)(topent & 0xffffffffu);
    float dnv = __fsqrt_rn(d2v);
    int rank = 0;
#pragma unroll
    for (int ml = 0; ml < SEL; ml++) {
        float dm = __shfl_sync(0xffffffffu, dnv, ml);
        int   jm = __shfl_sync(0xffffffffu, jv,  ml);
        if (ml != lane && (dm < dnv || (dm == dnv && jm < jv))) rank++;
    }
    if (lane < SEL && rank < TOPK) {
        g_idx[row * TOPK + rank] = jv;
        g_dn [row * TOPK + rank] = dnv;
    }
}

// ============================ MLP ============================
__global__ __launch_bounds__(128) void mlp_kernel(
    const float4* __restrict__ states,
    const float* __restrict__ W1, const float* __restrict__ b1,
    const float* __restrict__ b2, const float* __restrict__ b3,
    const float* __restrict__ W4, const float* __restrict__ b4,
    float* __restrict__ out, int out_size)
{
    __shared__ alignas(16) float xflat[72];       // [12 kk][6 cc]
    __shared__ alignas(16) float zA[64 * 12];     // z1 / z3
    __shared__ alignas(16) float zB[128 * 12];    // z2
    __shared__ alignas(16) u64   pz[128][BUFD];   // L3 split-K partials
    __shared__ float maskv[TOPK];
    __shared__ float sW4[64];
    __shared__ float sb4;

    const int t = threadIdx.x;
    if (t < 64) sW4[t] = W4[t];
    if (t == 64) sb4 = b4[0];

#pragma unroll 1
    for (int sub = 0; sub < 8; sub++) {
        const int a = blockIdx.x * 8 + sub;
        __syncthreads();

        if (t < TOPK) {
            int   idx = g_idx[a * TOPK + t];
            float dn  = g_dn [a * TOPK + t];
            float4 si = states[a];
            float4 sj = states[idx];
            xflat[t * 6 + 0] = __fsub_rn(si.x, sj.x);
            xflat[t * 6 + 1] = __fsub_rn(si.y, sj.y);
            xflat[t * 6 + 2] = __fsub_rn(si.z, sj.z);
            xflat[t * 6 + 3] = __fsub_rn(si.w, sj.w);
            xflat[t * 6 + 4] = (idx == a) ? 1.0f : 0.0f;
            xflat[t * 6 + 5] = __fsub_rn(dn, 0.8f);
            maskv[t] = (dn <= 1.0f) ? 1.0f : 0.0f;
        }
        __syncthreads();

        // layer 1: 6 -> 64   (h0[i][l] = xflat[i*12+l], reference reshape)
        if (t < 64) {
            u64 acc[6];
            u64 bb = pack2(b1[t]);
#pragma unroll
            for (int p = 0; p < 6; p++) acc[p] = bb;
            const u64* xu = reinterpret_cast<const u64*>(xflat);
#pragma unroll
            for (int i = 0; i < 6; i++) {
                u64 w = pack2(W1[t * 6 + i]);
#pragma unroll
                for (int p = 0; p < 6; p++) ffma2(acc[p], w, xu[i * 6 + p]);
            }
#pragma unroll
            for (int p = 0; p < 6; p++) {
                float2 u = unpack2(acc[p]);
                zA[t * 12 + 2 * p]     = fmaxf(u.x, 0.0f);
                zA[t * 12 + 2 * p + 1] = fmaxf(u.y, 0.0f);
            }
        }
        __syncthreads();

        // layer 2: 64 -> 128
        {
            u64 acc[6];
            u64 bb = pack2(b2[t]);
#pragma unroll
            for (int p = 0; p < 6; p++) acc[p] = bb;
            const ulonglong2* zv = reinterpret_cast<const ulonglong2*>(zA);
#pragma unroll 4
            for (int i = 0; i < 64; i++) {
                u64 w = pack2(g_W2t[i * 128 + t]);
                ulonglong2 p0 = zv[i * 3 + 0];
                ulonglong2 p1 = zv[i * 3 + 1];
                ulonglong2 p2 = zv[i * 3 + 2];
                ffma2(acc[0], w, p0.x); ffma2(acc[1], w, p0.y);
                ffma2(acc[2], w, p1.x); ffma2(acc[3], w, p1.y);
                ffma2(acc[4], w, p2.x); ffma2(acc[5], w, p2.y);
            }
#pragma unroll
            for (int p = 0; p < 6; p++) {
                float2 u = unpack2(acc[p]);
                zB[t * 12 + 2 * p]     = fmaxf(u.x, 0.0f);
                zB[t * 12 + 2 * p + 1] = fmaxf(u.y, 0.0f);
            }
        }
        __syncthreads();

        // layer 3: 128 -> 64 (split-K across thread halves)
        {
            int oc = t & 63, hh = t >> 6;
            u64 acc[6];
            u64 bb = (hh == 0) ? pack2(b3[oc]) : 0ULL;
#pragma unroll
            for (int p = 0; p < 6; p++) acc[p] = bb;
            const ulonglong2* zv = reinterpret_cast<const ulonglong2*>(zB);
#pragma unroll 4
            for (int ii = 0; ii < 64; ii++) {
                int i = hh * 64 + ii;
                u64 w = pack2(g_W3t[i * 64 + oc]);
                ulonglong2 p0 = zv[i * 3 + 0];
                ulonglong2 p1 = zv[i * 3 + 1];
                ulonglong2 p2 = zv[i * 3 + 2];
                ffma2(acc[0], w, p0.x); ffma2(acc[1], w, p0.y);
                ffma2(acc[2], w, p1.x); ffma2(acc[3], w, p1.y);
                ffma2(acc[4], w, p2.x); ffma2(acc[5], w, p2.y);
            }
#pragma unroll
            for (int p = 0; p < 6; p++) pz[t][p] = acc[p];
        }
        __syncthreads();
        if (t < 64) {
#pragma unroll
            for (int p = 0; p < 6; p++) {
                float2 u = unpack2(pz[t][p]);
                float2 v = unpack2(pz[t + 64][p]);
                zA[t * 12 + 2 * p]     = fmaxf(u.x + v.x, 0.0f);
                zA[t * 12 + 2 * p + 1] = fmaxf(u.y + v.y, 0.0f);
            }
        }
        __syncthreads();

        // layer 4: 64 -> 1, mask, write out
        if (t < TOPK) {
            float acc = sb4;
#pragma unroll 8
            for (int o = 0; o < 64; o++) acc += sW4[o] * zA[o * 12 + t];
            float mv = maskv[t];
            out[a * TOPK + t] = acc * mv;
            if (out_size >= 2 * N_AGENTS * TOPK)
                out[N_AGENTS * TOPK + a * TOPK + t] = mv;
        }
    }
}

extern "C" void kernel_launch(void* const* d_in, const int* in_sizes, int n_in,
                              void* d_out, int out_size) {
    const float* states = (const float*)d_in[0];
    const float* W1 = (const float*)d_in[1];
    const float* b1 = (const float*)d_in[2];
    const float* W2 = (const float*)d_in[3];
    const float* b2 = (const float*)d_in[4];
    const float* W3 = (const float*)d_in[5];
    const float* b3 = (const float*)d_in[6];
    const float* W4 = (const float*)d_in[7];
    const float* b4 = (const float*)d_in[8];
    float* out = (float*)d_out;

    transpose_kernel<<<16, 512>>>(W2, W3);
    topk_kernel<<<N_AGENTS / WPB, 256>>>((const float4*)states);
    mlp_kernel<<<N_AGENTS / 8, 128>>>((const float4*)states,
                                      W1, b1, b2, b3, W4, b4, out, out_size);
}

// round 4
// speedup vs baseline: 1.2034x; 1.2034x over previous
#include <cuda_runtime.h>

typedef unsigned long long u64;

#define N_AGENTS 4096
#define TOPK 12
#define SEL 16
#define EPSC 1e-4f
#define WPB 16          // warps (rows) per topk block
#define BUFD 6
#define TOPK_BLOCKS (N_AGENTS / WPB)   // 256

__device__ float g_W2t[64 * 128];   // [i][o]
__device__ float g_W3t[128 * 64];   // [i][o]
__device__ int   g_idx[N_AGENTS * TOPK];
__device__ float g_dn [N_AGENTS * TOPK];

static __device__ __forceinline__ u64 umin64(u64 a, u64 b) { return a < b ? a : b; }
static __device__ __forceinline__ u64 pack2(float w) {
    u64 r; asm("mov.b64 %0, {%1, %1};" : "=l"(r) : "f"(w)); return r;
}
static __device__ __forceinline__ void ffma2(u64 &d, u64 a, u64 b) {
    asm("fma.rn.f32x2 %0, %1, %2, %0;" : "+l"(d) : "l"(a), "l"(b));
}
static __device__ __forceinline__ float2 unpack2(u64 v) {
    return make_float2(__uint_as_float((unsigned)v), __uint_as_float((unsigned)(v >> 32)));
}

// ============================ exact top-k (+fused weight transpose) ============================
static __device__ __forceinline__ void warp_merge(
    u64 &topent, u64 &thrkey, int &bcnt, u64 (*buf)[32], int lane)
{
    u64 v[BUFD];
#pragma unroll
    for (int s = 0; s < BUFD; s++) v[s] = (s < bcnt) ? buf[s][lane] : ~0ULL;
    u64 oldtop = topent;
    u64 newtop = ~0ULL;
#pragma unroll 1
    for (int r = 0; r < SEL; r++) {
        u64 lm = oldtop;
#pragma unroll
        for (int s = 0; s < BUFD; s++) lm = umin64(lm, v[s]);
#pragma unroll
        for (int o = 16; o > 0; o >>= 1)
            lm = umin64(lm, __shfl_xor_sync(0xffffffffu, lm, o));
        if (oldtop == lm) oldtop = ~0ULL;
#pragma unroll
        for (int s = 0; s < BUFD; s++) if (v[s] == lm) v[s] = ~0ULL;
        if (lane == r) newtop = lm;
        thrkey = lm;
    }
    topent = newtop;
    bcnt = 0;
}

__global__ __launch_bounds__(32 * WPB) void topk_kernel(
    const float4* __restrict__ states,
    const float* __restrict__ W2, const float* __restrict__ W3)
{
    // trailing block does the weight transposes instead of top-k
    if (blockIdx.x == TOPK_BLOCKS) {
        for (int t = threadIdx.x; t < 128 * 64; t += 32 * WPB) {
            int o2 = t / 64, i2 = t % 64;      // W2: [128][64]
            g_W2t[i2 * 128 + o2] = W2[t];
            int o3 = t / 128, i3 = t % 128;    // W3: [64][128]
            g_W3t[i3 * 64 + o3] = W3[t];
        }
        return;
    }

    __shared__ float2 sxy[N_AGENTS];
    __shared__ u64 sbuf[WPB][BUFD][32];

    for (int j = threadIdx.x; j < N_AGENTS; j += 32 * WPB) {
        float4 s = states[j];
        sxy[j] = make_float2(s.x, s.y);
    }
    __syncthreads();

    const int warp = threadIdx.x >> 5;
    const int lane = threadIdx.x & 31;
    const int row  = blockIdx.x * WPB + warp;
    const float xi = sxy[row].x, yi = sxy[row].y;

    u64 topent = ~0ULL, thrkey = ~0ULL;
    int bcnt = 0;

#pragma unroll 1
    for (int m = 0; m < N_AGENTS / 32; m++) {
        int j = m * 32 + lane;
        float2 sj = sxy[j];
        float dx = __fsub_rn(xi, sj.x);
        float dy = __fsub_rn(yi, sj.y);
        float pa = __fadd_rn(__fmul_rn(dx, dx), EPSC);
        float pb = __fadd_rn(__fmul_rn(dy, dy), EPSC);
        float d2 = __fadd_rn(pa, pb);
        u64 key = ((u64)__float_as_uint(d2) << 32) | (unsigned)j;
        if (key < thrkey) { sbuf[warp][bcnt][lane] = key; bcnt++; }
        if (__ballot_sync(0xffffffffu, bcnt == BUFD))
            warp_merge(topent, thrkey, bcnt, sbuf[warp], lane);
    }
    if (__ballot_sync(0xffffffffu, bcnt > 0))
        warp_merge(topent, thrkey, bcnt, sbuf[warp], lane);

    // re-rank survivors by (dn, idx) — JAX top_k tie semantics
    float d2v = __uint_as_float((unsigned)(topent >> 32));
    int   jv  = (int)(unsigned)(topent & 0xffffffffu);
    float dnv = __fsqrt_rn(d2v);
    int rank = 0;
#pragma unroll
    for (int ml = 0; ml < SEL; ml++) {
        float dm = __shfl_sync(0xffffffffu, dnv, ml);
        int   jm = __shfl_sync(0xffffffffu, jv,  ml);
        if (ml != lane && (dm < dnv || (dm == dnv && jm < jv))) rank++;
    }
    if (lane < SEL && rank < TOPK) {
        g_idx[row * TOPK + rank] = jv;
        g_dn [row * TOPK + rank] = dnv;
    }
}

// ============================ MLP: one agent per CTA ============================
__global__ __launch_bounds__(128) void mlp_kernel(
    const float4* __restrict__ states,
    const float* __restrict__ W1, const float* __restrict__ b1,
    const float* __restrict__ b2, const float* __restrict__ b3,
    const float* __restrict__ W4, const float* __restrict__ b4,
    float* __restrict__ out, int out_size)
{
    __shared__ alignas(16) float xflat[72];       // [12 kk][6 cc]
    __shared__ alignas(16) float zA[64 * 12];     // z1 / z3
    __shared__ alignas(16) float zB[128 * 12];    // z2
    __shared__ alignas(16) u64   pz[128][BUFD];   // L3 split-K partials
    __shared__ float maskv[TOPK];
    __shared__ float sW4[64];
    __shared__ float sb4;

    const int t = threadIdx.x;
    const int a = blockIdx.x;

    if (t < 64) sW4[t] = W4[t];
    if (t == 64) sb4 = b4[0];

    if (t < TOPK) {
        int   idx = g_idx[a * TOPK + t];
        float dn  = g_dn [a * TOPK + t];
        float4 si = states[a];
        float4 sj = states[idx];
        xflat[t * 6 + 0] = __fsub_rn(si.x, sj.x);
        xflat[t * 6 + 1] = __fsub_rn(si.y, sj.y);
        xflat[t * 6 + 2] = __fsub_rn(si.z, sj.z);
        xflat[t * 6 + 3] = __fsub_rn(si.w, sj.w);
        xflat[t * 6 + 4] = (idx == a) ? 1.0f : 0.0f;
        xflat[t * 6 + 5] = __fsub_rn(dn, 0.8f);
        maskv[t] = (dn <= 1.0f) ? 1.0f : 0.0f;
    }
    __syncthreads();

    // layer 1: 6 -> 64   (h0[i][l] = xflat[i*12+l], reference reshape)
    if (t < 64) {
        u64 acc[6];
        u64 bb = pack2(b1[t]);
#pragma unroll
        for (int p = 0; p < 6; p++) acc[p] = bb;
        const u64* xu = reinterpret_cast<const u64*>(xflat);
#pragma unroll
        for (int i = 0; i < 6; i++) {
            u64 w = pack2(W1[t * 6 + i]);
#pragma unroll
            for (int p = 0; p < 6; p++) ffma2(acc[p], w, xu[i * 6 + p]);
        }
#pragma unroll
        for (int p = 0; p < 6; p++) {
            float2 u = unpack2(acc[p]);
            zA[t * 12 + 2 * p]     = fmaxf(u.x, 0.0f);
            zA[t * 12 + 2 * p + 1] = fmaxf(u.y, 0.0f);
        }
    }
    __syncthreads();

    // layer 2: 64 -> 128
    {
        u64 acc[6];
        u64 bb = pack2(b2[t]);
#pragma unroll
        for (int p = 0; p < 6; p++) acc[p] = bb;
        const ulonglong2* zv = reinterpret_cast<const ulonglong2*>(zA);
#pragma unroll 4
        for (int i = 0; i < 64; i++) {
            u64 w = pack2(g_W2t[i * 128 + t]);
            ulonglong2 p0 = zv[i * 3 + 0];
            ulonglong2 p1 = zv[i * 3 + 1];
            ulonglong2 p2 = zv[i * 3 + 2];
            ffma2(acc[0], w, p0.x); ffma2(acc[1], w, p0.y);
            ffma2(acc[2], w, p1.x); ffma2(acc[3], w, p1.y);
            ffma2(acc[4], w, p2.x); ffma2(acc[5], w, p2.y);
        }
#pragma unroll
        for (int p = 0; p < 6; p++) {
            float2 u = unpack2(acc[p]);
            zB[t * 12 + 2 * p]     = fmaxf(u.x, 0.0f);
            zB[t * 12 + 2 * p + 1] = fmaxf(u.y, 0.0f);
        }
    }
    __syncthreads();

    // layer 3: 128 -> 64 (split-K across thread halves)
    {
        int oc = t & 63, hh = t >> 6;
        u64 acc[6];
        u64 bb = (hh == 0) ? pack2(b3[oc]) : 0ULL;
#pragma unroll
        for (int p = 0; p < 6; p++) acc[p] = bb;
        const ulonglong2* zv = reinterpret_cast<const ulonglong2*>(zB);
#pragma unroll 4
        for (int ii = 0; ii < 64; ii++) {
            int i = hh * 64 + ii;
            u64 w = pack2(g_W3t[i * 64 + oc]);
            ulonglong2 p0 = zv[i * 3 + 0];
            ulonglong2 p1 = zv[i * 3 + 1];
            ulonglong2 p2 = zv[i * 3 + 2];
            ffma2(acc[0], w, p0.x); ffma2(acc[1], w, p0.y);
            ffma2(acc[2], w, p1.x); ffma2(acc[3], w, p1.y);
            ffma2(acc[4], w, p2.x); ffma2(acc[5], w, p2.y);
        }
#pragma unroll
        for (int p = 0; p < 6; p++) pz[t][p] = acc[p];
    }
    __syncthreads();
    if (t < 64) {
#pragma unroll
        for (int p = 0; p < 6; p++) {
            float2 u = unpack2(pz[t][p]);
            float2 v = unpack2(pz[t + 64][p]);
            zA[t * 12 + 2 * p]     = fmaxf(u.x + v.x, 0.0f);
            zA[t * 12 + 2 * p + 1] = fmaxf(u.y + v.y, 0.0f);
        }
    }
    __syncthreads();

    // layer 4: 64 -> 1, mask, write out (4 independent accumulators)
    if (t < TOPK) {
        float a0 = sb4, a1 = 0.f, a2 = 0.f, a3 = 0.f;
#pragma unroll
        for (int o = 0; o < 64; o += 4) {
            a0 += sW4[o]     * zA[(o)     * 12 + t];
            a1 += sW4[o + 1] * zA[(o + 1) * 12 + t];
            a2 += sW4[o + 2] * zA[(o + 2) * 12 + t];
            a3 += sW4[o + 3] * zA[(o + 3) * 12 + t];
        }
        float acc = (a0 + a1) + (a2 + a3);
        float mv = maskv[t];
        out[a * TOPK + t] = acc * mv;
        if (out_size >= 2 * N_AGENTS * TOPK)
            out[N_AGENTS * TOPK + a * TOPK + t] = mv;
    }
}

extern "C" void kernel_launch(void* const* d_in, const int* in_sizes, int n_in,
                              void* d_out, int out_size) {
    const float* states = (const float*)d_in[0];
    const float* W1 = (const float*)d_in[1];
    const float* b1 = (const float*)d_in[2];
    const float* W2 = (const float*)d_in[3];
    const float* b2 = (const float*)d_in[4];
    const float* W3 = (const float*)d_in[5];
    const float* b3 = (const float*)d_in[6];
    const float* W4 = (const float*)d_in[7];
    const float* b4 = (const float*)d_in[8];
    float* out = (float*)d_out;

    // 256 topk blocks (16 rows each) + 1 trailing block that transposes W2/W3
    topk_kernel<<<TOPK_BLOCKS + 1, 32 * WPB>>>((const float4*)states, W2, W3);
    mlp_kernel<<<N_AGENTS, 128>>>((const float4*)states,
                                  W1, b1, b2, b3, W4, b4, out, out_size);
}

// round 5
// speedup vs baseline: 1.3739x; 1.1417x over previous
#include <cuda_runtime.h>

typedef unsigned long long u64;

#define N_AGENTS 4096
#define TOPK 12
#define SEL 16
#define EPSC 1e-4f
#define TWPB 8                         // warps (rows) per topk block
#define BUFD 6
#define TOPK_BLOCKS (N_AGENTS / TWPB)  // 512

__device__ float4 g_W2p[64 * 32];      // [i][lane] -> w2 for outputs lane+{0,32,64,96}
__device__ float2 g_W3p[128 * 32];     // [i][lane] -> w3 for outputs lane+{0,32}
__device__ float2 g_W1p[6 * 32];       // [i][lane] -> w1 for outputs lane+{0,32}
__device__ int    g_idx[N_AGENTS * TOPK];
__device__ float  g_dn [N_AGENTS * TOPK];

static __device__ __forceinline__ u64 umin64(u64 a, u64 b) { return a < b ? a : b; }
static __device__ __forceinline__ u64 pack2(float w) {
    u64 r; asm("mov.b64 %0, {%1, %1};" : "=l"(r) : "f"(w)); return r;
}
static __device__ __forceinline__ void ffma2(u64 &d, u64 a, u64 b) {
    asm("fma.rn.f32x2 %0, %1, %2, %0;" : "+l"(d) : "l"(a), "l"(b));
}
static __device__ __forceinline__ float2 unpack2(u64 v) {
    return make_float2(__uint_as_float((unsigned)v), __uint_as_float((unsigned)(v >> 32)));
}

// ============================ exact top-k (+fused weight packing) ============================
static __device__ __forceinline__ void warp_merge(
    u64 &topent, u64 &thrkey, int &bcnt, u64 (*buf)[32], int lane)
{
    u64 v[BUFD];
#pragma unroll
    for (int s = 0; s < BUFD; s++) v[s] = (s < bcnt) ? buf[s][lane] : ~0ULL;
    u64 oldtop = topent;
    u64 newtop = ~0ULL;
#pragma unroll 1
    for (int r = 0; r < SEL; r++) {
        u64 lm = oldtop;
#pragma unroll
        for (int s = 0; s < BUFD; s++) lm = umin64(lm, v[s]);
#pragma unroll
        for (int o = 16; o > 0; o >>= 1)
            lm = umin64(lm, __shfl_xor_sync(0xffffffffu, lm, o));
        if (oldtop == lm) oldtop = ~0ULL;
#pragma unroll
        for (int s = 0; s < BUFD; s++) if (v[s] == lm) v[s] = ~0ULL;
        if (lane == r) newtop = lm;
        thrkey = lm;
    }
    topent = newtop;
    bcnt = 0;
}

__global__ __launch_bounds__(32 * TWPB) void topk_kernel(
    const float4* __restrict__ states,
    const float* __restrict__ W1, const float* __restrict__ W2,
    const float* __restrict__ W3)
{
    // trailing block: pack weights into lane-major layouts
    if (blockIdx.x == TOPK_BLOCKS) {
        float* w2p = (float*)g_W2p;
        float* w3p = (float*)g_W3p;
        float* w1p = (float*)g_W1p;
        for (int t = threadIdx.x; t < 8192; t += 32 * TWPB) {
            { int i = t >> 7, rem = t & 127, lane = rem >> 2, q = rem & 3;
              w2p[t] = W2[(lane + 32 * q) * 64 + i]; }      // W2: [128 o][64 i]
            { int i = t >> 6, rem = t & 63, lane = rem >> 1, q = rem & 1;
              w3p[t] = W3[(lane + 32 * q) * 128 + i]; }     // W3: [64 o][128 i]
            if (t < 384) {
              int i = t >> 6, rem = t & 63, lane = rem >> 1, q = rem & 1;
              w1p[t] = W1[(lane + 32 * q) * 6 + i];         // W1: [64 o][6 i]
            }
        }
        return;
    }

    __shared__ u64 sbuf[TWPB][BUFD][32];

    const int warp = threadIdx.x >> 5;
    const int lane = threadIdx.x & 31;
    const int row  = blockIdx.x * TWPB + warp;
    float4 sr = states[row];
    const float xi = sr.x, yi = sr.y;

    u64 topent = ~0ULL, thrkey = ~0ULL;
    int bcnt = 0;

#pragma unroll 1
    for (int m = 0; m < N_AGENTS / 32; m++) {
        float4 sj = states[m * 32 + lane];
        float dx = __fsub_rn(xi, sj.x);
        float dy = __fsub_rn(yi, sj.y);
        float pa = __fadd_rn(__fmul_rn(dx, dx), EPSC);
        float pb = __fadd_rn(__fmul_rn(dy, dy), EPSC);
        float d2 = __fadd_rn(pa, pb);
        u64 key = ((u64)__float_as_uint(d2) << 32) | (unsigned)(m * 32 + lane);
        if (key < thrkey) { sbuf[warp][bcnt][lane] = key; bcnt++; }
        if (__ballot_sync(0xffffffffu, bcnt == BUFD))
            warp_merge(topent, thrkey, bcnt, sbuf[warp], lane);
    }
    if (__ballot_sync(0xffffffffu, bcnt > 0))
        warp_merge(topent, thrkey, bcnt, sbuf[warp], lane);

    // re-rank survivors by (dn, idx) — JAX top_k tie semantics
    float d2v = __uint_as_float((unsigned)(topent >> 32));
    int   jv  = (int)(unsigned)(topent & 0xffffffffu);
    float dnv = __fsqrt_rn(d2v);
    int rank = 0;
#pragma unroll
    for (int ml = 0; ml < SEL; ml++) {
        float dm = __shfl_sync(0xffffffffu, dnv, ml);
        int   jm = __shfl_sync(0xffffffffu, jv,  ml);
        if (ml != lane && (dm < dnv || (dm == dnv && jm < jv))) rank++;
    }
    if (lane < SEL && rank < TOPK) {
        g_idx[row * TOPK + rank] = jv;
        g_dn [row * TOPK + rank] = dnv;
    }
}

// ============================ MLP: warp per agent, register-blocked ============================
__global__ __launch_bounds__(128) void mlp_kernel(
    const float4* __restrict__ states,
    const float* __restrict__ b1, const float* __restrict__ b2,
    const float* __restrict__ b3,
    const float* __restrict__ W4, const float* __restrict__ b4,
    float* __restrict__ out, int out_size)
{
    __shared__ alignas(16) float xflat_s[4][80];    // [12 kk][6 cc] (+pad)
    __shared__ alignas(16) float zA_s[4][768];      // z1 [64][12]; reused as z3t [12][64]
    __shared__ alignas(16) float zB_s[4][1536];     // z2 [128][12]

    const int t = threadIdx.x;
    const int w = t >> 5;
    const int lane = t & 31;
    const int a = blockIdx.x * 4 + w;

    float* xflat = xflat_s[w];
    float* zA = zA_s[w];
    float* zB = zB_s[w];

    float maskr = 0.0f;
    if (lane < TOPK) {
        int   idx = g_idx[a * TOPK + lane];
        float dn  = g_dn [a * TOPK + lane];
        float4 si = states[a];
        float4 sj = states[idx];
        xflat[lane * 6 + 0] = __fsub_rn(si.x, sj.x);
        xflat[lane * 6 + 1] = __fsub_rn(si.y, sj.y);
        xflat[lane * 6 + 2] = __fsub_rn(si.z, sj.z);
        xflat[lane * 6 + 3] = __fsub_rn(si.w, sj.w);
        xflat[lane * 6 + 4] = (idx == a) ? 1.0f : 0.0f;
        xflat[lane * 6 + 5] = __fsub_rn(dn, 0.8f);
        maskr = (dn <= 1.0f) ? 1.0f : 0.0f;
    }
    __syncwarp();

    // ---- layer 1: 6 -> 64, 2 outputs/lane (o = lane, lane+32) ----
    {
        u64 acc[12];
        u64 bb0 = pack2(b1[lane]), bb1 = pack2(b1[lane + 32]);
#pragma unroll
        for (int p = 0; p < 6; p++) { acc[p] = bb0; acc[6 + p] = bb1; }
        const u64* xu = reinterpret_cast<const u64*>(xflat);
#pragma unroll
        for (int i = 0; i < 6; i++) {
            float2 wv = g_W1p[i * 32 + lane];
            u64 w0 = pack2(wv.x), w1 = pack2(wv.y);
#pragma unroll
            for (int p = 0; p < 6; p++) {
                u64 xp = xu[i * 6 + p];
                ffma2(acc[p], w0, xp);
                ffma2(acc[6 + p], w1, xp);
            }
        }
        float2* zA2 = reinterpret_cast<float2*>(zA);
#pragma unroll
        for (int p = 0; p < 6; p++) {
            float2 u = unpack2(acc[p]);
            zA2[lane * 6 + p] = make_float2(fmaxf(u.x, 0.f), fmaxf(u.y, 0.f));
            float2 v = unpack2(acc[6 + p]);
            zA2[(lane + 32) * 6 + p] = make_float2(fmaxf(v.x, 0.f), fmaxf(v.y, 0.f));
        }
    }
    __syncwarp();

    // ---- layer 2: 64 -> 128, 4 outputs/lane (o = lane+32q) ----
    {
        u64 acc[24];
#pragma unroll
        for (int q = 0; q < 4; q++) {
            u64 bb = pack2(b2[lane + 32 * q]);
#pragma unroll
            for (int p = 0; p < 6; p++) acc[q * 6 + p] = bb;
        }
        const ulonglong2* zv = reinterpret_cast<const ulonglong2*>(zA);
#pragma unroll 2
        for (int i = 0; i < 64; i++) {
            float4 wv = g_W2p[i * 32 + lane];
            u64 w0 = pack2(wv.x), w1 = pack2(wv.y), w2 = pack2(wv.z), w3 = pack2(wv.w);
            ulonglong2 p0 = zv[i * 3 + 0];
            ulonglong2 p1 = zv[i * 3 + 1];
            ulonglong2 p2 = zv[i * 3 + 2];
            ffma2(acc[0],  w0, p0.x); ffma2(acc[1],  w0, p0.y);
            ffma2(acc[2],  w0, p1.x); ffma2(acc[3],  w0, p1.y);
            ffma2(acc[4],  w0, p2.x); ffma2(acc[5],  w0, p2.y);
            ffma2(acc[6],  w1, p0.x); ffma2(acc[7],  w1, p0.y);
            ffma2(acc[8],  w1, p1.x); ffma2(acc[9],  w1, p1.y);
            ffma2(acc[10], w1, p2.x); ffma2(acc[11], w1, p2.y);
            ffma2(acc[12], w2, p0.x); ffma2(acc[13], w2, p0.y);
            ffma2(acc[14], w2, p1.x); ffma2(acc[15], w2, p1.y);
            ffma2(acc[16], w2, p2.x); ffma2(acc[17], w2, p2.y);
            ffma2(acc[18], w3, p0.x); ffma2(acc[19], w3, p0.y);
            ffma2(acc[20], w3, p1.x); ffma2(acc[21], w3, p1.y);
            ffma2(acc[22], w3, p2.x); ffma2(acc[23], w3, p2.y);
        }
        float2* zB2 = reinterpret_cast<float2*>(zB);
#pragma unroll
        for (int q = 0; q < 4; q++) {
#pragma unroll
            for (int p = 0; p < 6; p++) {
                float2 u = unpack2(acc[q * 6 + p]);
                zB2[(lane + 32 * q) * 6 + p] =
                    make_float2(fmaxf(u.x, 0.f), fmaxf(u.y, 0.f));
            }
        }
    }
    __syncwarp();

    // ---- layer 3: 128 -> 64, 2 outputs/lane; store transposed z3t[L][64] ----
    float* z3t = zA;   // reuse
    {
        u64 acc[12];
        u64 bb0 = pack2(b3[lane]), bb1 = pack2(b3[lane + 32]);
#pragma unroll
        for (int p = 0; p < 6; p++) { acc[p] = bb0; acc[6 + p] = bb1; }
        const ulonglong2* zv = reinterpret_cast<const ulonglong2*>(zB);
#pragma unroll 2
        for (int i = 0; i < 128; i++) {
            float2 wv = g_W3p[i * 32 + lane];
            u64 w0 = pack2(wv.x), w1 = pack2(wv.y);
            ulonglong2 p0 = zv[i * 3 + 0];
            ulonglong2 p1 = zv[i * 3 + 1];
            ulonglong2 p2 = zv[i * 3 + 2];
            ffma2(acc[0],  w0, p0.x); ffma2(acc[1],  w0, p0.y);
            ffma2(acc[2],  w0, p1.x); ffma2(acc[3],  w0, p1.y);
            ffma2(acc[4],  w0, p2.x); ffma2(acc[5],  w0, p2.y);
            ffma2(acc[6],  w1, p0.x); ffma2(acc[7],  w1, p0.y);
            ffma2(acc[8],  w1, p1.x); ffma2(acc[9],  w1, p1.y);
            ffma2(acc[10], w1, p2.x); ffma2(acc[11], w1, p2.y);
        }
        __syncwarp();   // everyone done READING zA (aliased) before overwrite
#pragma unroll
        for (int p = 0; p < 6; p++) {
            float2 u = unpack2(acc[p]);
            z3t[(2 * p)     * 64 + lane] = fmaxf(u.x, 0.f);
            z3t[(2 * p + 1) * 64 + lane] = fmaxf(u.y, 0.f);
            float2 v = unpack2(acc[6 + p]);
            z3t[(2 * p)     * 64 + lane + 32] = fmaxf(v.x, 0.f);
            z3t[(2 * p + 1) * 64 + lane + 32] = fmaxf(v.y, 0.f);
        }
    }
    __syncwarp();

    // ---- layer 4: 64 -> 1 per L, mask, write ----
    if (lane < TOPK) {
        const float4* zv = reinterpret_cast<const float4*>(z3t) + lane * 16;
        const float4* wv = reinterpret_cast<const float4*>(W4);
        float a0 = b4[0], a1 = 0.f, a2 = 0.f, a3 = 0.f;
#pragma unroll
        for (int oc = 0; oc < 16; oc++) {
            float4 z = zv[oc];
            float4 ww = wv[oc];
            a0 = fmaf(ww.x, z.x, a0);
            a1 = fmaf(ww.y, z.y, a1);
            a2 = fmaf(ww.z, z.z, a2);
            a3 = fmaf(ww.w, z.w, a3);
        }
        float acc = (a0 + a1) + (a2 + a3);
        out[a * TOPK + lane] = acc * maskr;
        if (out_size >= 2 * N_AGENTS * TOPK)
            out[N_AGENTS * TOPK + a * TOPK + lane] = maskr;
    }
}

extern "C" void kernel_launch(void* const* d_in, const int* in_sizes, int n_in,
                              void* d_out, int out_size) {
    const float* states = (const float*)d_in[0];
    const float* W1 = (const float*)d_in[1];
    const float* b1 = (const float*)d_in[2];
    const float* W2 = (const float*)d_in[3];
    const float* b2 = (const float*)d_in[4];
    const float* W3 = (const float*)d_in[5];
    const float* b3 = (const float*)d_in[6];
    const float* W4 = (const float*)d_in[7];
    const float* b4 = (const float*)d_in[8];
    float* out = (float*)d_out;

    // 512 topk blocks (8 rows each) + 1 trailing block packing W1/W2/W3
    topk_kernel<<<TOPK_BLOCKS + 1, 32 * TWPB>>>((const float4*)states, W1, W2, W3);
    // 1024 CTAs x 4 warps = 4096 agents, one warp per agent
    mlp_kernel<<<N_AGENTS / 4, 128>>>((const float4*)states,
                                      b1, b2, b3, W4, b4, out, out_size);
}